// round 1
// baseline (speedup 1.0000x reference)
#include <cuda_runtime.h>
#include <cuda_bf16.h>
#include <cstdint>

// PrRoIPool2D(7,7, spatial_scale=0.5)
// features: (N=8, C=256, H=56, W=56) f32
// rois:     (R=256, 5) f32  [b, x1, y1, x2, y2] in image coords
// out:      (R, C, 7, 7) f32

#define POOLED 7
#define SCALE 0.5f
#define CC 256
#define HH 56
#define WW 56

// Antiderivative of tent max(0,1-|t|) with G(-1)=0, t pre-clipped to [-1,1]
__device__ __forceinline__ float tentG(float t) {
    float u;
    if (t <= 0.0f) { u = t + 1.0f; return 0.5f * u * u; }
    u = 1.0f - t;
    return 1.0f - 0.5f * u * u;
}

__device__ __forceinline__ float tent_int(float start, float end, float i) {
    float a = fminf(fmaxf(start - i, -1.0f), 1.0f);
    float b = fminf(fmaxf(end   - i, -1.0f), 1.0f);
    return tentG(b) - tentG(a);
}

__global__ __launch_bounds__(256, 2)
void prroi_kernel(const float* __restrict__ feat,
                  const float* __restrict__ rois,
                  float* __restrict__ out,
                  int R)
{
    const int r = blockIdx.x;
    const int c = threadIdx.x;

    __shared__ float sIx[POOLED][WW];
    __shared__ float sIy[POOLED][HH];
    __shared__ int   swlo[POOLED], swhi[POOLED];
    __shared__ int   s_hlo, s_hhi, s_b;
    __shared__ float s_scale;

    // ---- per-ROI setup (uniform across block) ----
    const float rb  = rois[r * 5 + 0];
    const float rx1 = rois[r * 5 + 1] * SCALE;
    const float ry1 = rois[r * 5 + 2] * SCALE;
    const float rx2 = rois[r * 5 + 3] * SCALE;
    const float ry2 = rois[r * 5 + 4] * SCALE;
    const float bw = (rx2 - rx1) * (1.0f / POOLED);
    const float bh = (ry2 - ry1) * (1.0f / POOLED);

    if (threadIdx.x == 0) {
        s_b   = (int)rb;
        int hlo = (int)ceilf(ry1 - 1.0f); if (hlo < 0) hlo = 0;
        int hhi = (int)floorf(ry2 + 1.0f); if (hhi > HH - 1) hhi = HH - 1;
        s_hlo = hlo; s_hhi = hhi;
        float area = bw * bh;
        s_scale = (area > 0.0f) ? (1.0f / fmaxf(area, 1e-12f)) : 0.0f;
    }
    if (threadIdx.x < POOLED) {
        int q = threadIdx.x;
        float xs = rx1 + q * bw;
        int wlo = (int)ceilf(xs - 1.0f);           if (wlo < 0) wlo = 0;
        int whi = (int)floorf(xs + bw + 1.0f);     if (whi > WW - 1) whi = WW - 1;
        swlo[q] = wlo; swhi[q] = whi;
    }
    // fill integral tables: 7*56 entries each
    for (int t = threadIdx.x; t < POOLED * WW; t += blockDim.x) {
        int q = t / WW, w = t - q * WW;
        float xs = rx1 + q * bw;
        sIx[q][w] = tent_int(xs, xs + bw, (float)w);
        float ys = ry1 + q * bh;
        sIy[q][w] = tent_int(ys, ys + bh, (float)w);
    }
    __syncthreads();

    const int hlo = s_hlo, hhi = s_hhi;
    const float* __restrict__ F =
        feat + ((size_t)s_b * CC + c) * (HH * WW);

    float acc[POOLED * POOLED];
#pragma unroll
    for (int k = 0; k < POOLED * POOLED; ++k) acc[k] = 0.0f;

    for (int h = hlo; h <= hhi; ++h) {
        const float* __restrict__ Frow = F + h * WW;
        float tq[POOLED];
#pragma unroll
        for (int q = 0; q < POOLED; ++q) {
            float s = 0.0f;
            const int wl = swlo[q], wh = swhi[q];
            for (int w = wl; w <= wh; ++w)
                s = fmaf(Frow[w], sIx[q][w], s);
            tq[q] = s;
        }
#pragma unroll
        for (int ph = 0; ph < POOLED; ++ph) {
            const float iy = sIy[ph][h];
            if (iy != 0.0f) {
#pragma unroll
                for (int pw = 0; pw < POOLED; ++pw)
                    acc[ph * POOLED + pw] = fmaf(iy, tq[pw], acc[ph * POOLED + pw]);
            }
        }
    }

    const float sc = s_scale;
    float* __restrict__ o = out + ((size_t)r * CC + c) * (POOLED * POOLED);
#pragma unroll
    for (int k = 0; k < POOLED * POOLED; ++k)
        o[k] = acc[k] * sc;
}

extern "C" void kernel_launch(void* const* d_in, const int* in_sizes, int n_in,
                              void* d_out, int out_size) {
    const float* feat = (const float*)d_in[0];
    const float* rois = (const float*)d_in[1];
    float* out = (float*)d_out;
    const int R = in_sizes[1] / 5;
    prroi_kernel<<<R, 256>>>(feat, rois, out, R);
}

// round 2
// speedup vs baseline: 2.7795x; 2.7795x over previous
#include <cuda_runtime.h>
#include <cuda_bf16.h>
#include <cstdint>

// PrRoIPool2D(7,7, spatial_scale=0.5)
// features: (N=8, C=256, H=56, W=56) f32
// rois:     (R=256, 5) f32  [b, x1, y1, x2, y2] image coords
// out:      (R, C, 7, 7) f32

#define POOLED 7
#define SCALE 0.5f
#define CC 256
#define HH 56
#define WW 56
#define WWP 80   // padded Ix width (zeros beyond 55) so dense window never OOB

// Antiderivative of tent max(0,1-|t|) with G(-1)=0, t pre-clipped to [-1,1]
__device__ __forceinline__ float tentG(float t) {
    float u;
    if (t <= 0.0f) { u = t + 1.0f; return 0.5f * u * u; }
    u = 1.0f - t;
    return 1.0f - 0.5f * u * u;
}

__device__ __forceinline__ float tent_int(float s, float e, float i) {
    float a = fminf(fmaxf(s - i, -1.0f), 1.0f);
    float b = fminf(fmaxf(e - i, -1.0f), 1.0f);
    return tentG(b) - tentG(a);
}

__global__ __launch_bounds__(64, 8)
void prroi_kernel(const float* __restrict__ feat,
                  const float* __restrict__ rois,
                  float* __restrict__ out)
{
    const int bx = blockIdx.x;
    const int r  = bx >> 2;                       // ROI index
    const int c  = ((bx & 3) << 6) + threadIdx.x; // channel (4 groups of 64)

    __shared__ float sIx[POOLED][WWP];
    __shared__ float sIy[POOLED][HH];

    // ---- per-ROI setup (uniform across block; broadcast loads) ----
    const float rb  = rois[r * 5 + 0];
    const float rx1 = rois[r * 5 + 1] * SCALE;
    const float ry1 = rois[r * 5 + 2] * SCALE;
    const float rx2 = rois[r * 5 + 3] * SCALE;
    const float ry2 = rois[r * 5 + 4] * SCALE;
    const float bw = (rx2 - rx1) * (1.0f / POOLED);
    const float bh = (ry2 - ry1) * (1.0f / POOLED);
    const float area = bw * bh;
    const float sc = (area > 0.0f) ? (1.0f / fmaxf(area, 1e-12f)) : 0.0f;

    // x-integral table, zero-padded to WWP so the dense register window is safe
    for (int t = threadIdx.x; t < POOLED * WWP; t += 64) {
        int q = t / WWP, w = t - q * WWP;
        float xs = rx1 + q * bw;
        sIx[q][w] = (w < WW) ? tent_int(xs, xs + bw, (float)w) : 0.0f;
    }
    // y-integral table with 1/area folded in
    for (int t = threadIdx.x; t < POOLED * HH; t += 64) {
        int q = t / HH, hh = t - q * HH;
        float ys = ry1 + q * bh;
        sIy[q][hh] = sc * tent_int(ys, ys + bh, (float)hh);
    }
    __syncthreads();

    int hlo = (int)ceilf(ry1 - 1.0f);  if (hlo < 0) hlo = 0;
    int hhi = (int)floorf(ry2 + 1.0f); if (hhi > HH - 1) hhi = HH - 1;
    int wlo = (int)ceilf(rx1 - 1.0f);  if (wlo < 0) wlo = 0;
    const int wbase = wlo & ~3;        // float4-aligned window start
    const int base4 = wbase >> 2;

    // Feature row pointers: row stride 56 floats = 224 B (16B aligned)
    const float4* __restrict__ F4 =
        (const float4*)(feat + ((size_t)(int)rb * CC + c) * (HH * WW));

    float acc[49];
#pragma unroll
    for (int k = 0; k < 49; ++k) acc[k] = 0.0f;

    for (int h = hlo; h <= hhi; ++h) {
        const float4* __restrict__ row = F4 + h * (WW / 4);
        // 7 independent vector loads: full x-support window (<= 27 floats)
        float4 win[7];
#pragma unroll
        for (int j = 0; j < 7; ++j) {
            int i4 = base4 + j;
            i4 = (i4 < (WW / 4 - 1)) ? i4 : (WW / 4 - 1);  // clamp in-row; Ix pad=0 kills extras
            win[j] = row[i4];
        }
        // dense 28-tap x-integrals for all 7 bins (fully unrolled)
        float tq[7];
#pragma unroll
        for (int q = 0; q < 7; ++q) {
            const float* __restrict__ ix = &sIx[q][wbase];  // 16B-aligned (wbase%4==0)
            float s = 0.0f;
#pragma unroll
            for (int j = 0; j < 7; ++j) {
                s = fmaf(win[j].x, ix[4 * j + 0], s);
                s = fmaf(win[j].y, ix[4 * j + 1], s);
                s = fmaf(win[j].z, ix[4 * j + 2], s);
                s = fmaf(win[j].w, ix[4 * j + 3], s);
            }
            tq[q] = s;
        }
        // y accumulation (iy==0 rows skipped; uniform branch, no divergence)
#pragma unroll
        for (int ph = 0; ph < 7; ++ph) {
            const float iy = sIy[ph][h];
            if (iy != 0.0f) {
#pragma unroll
                for (int pw = 0; pw < 7; ++pw)
                    acc[ph * 7 + pw] = fmaf(iy, tq[pw], acc[ph * 7 + pw]);
            }
        }
    }

    float* __restrict__ o = out + ((size_t)r * CC + c) * 49;
#pragma unroll
    for (int k = 0; k < 49; ++k) o[k] = acc[k];
}

extern "C" void kernel_launch(void* const* d_in, const int* in_sizes, int n_in,
                              void* d_out, int out_size) {
    const float* feat = (const float*)d_in[0];
    const float* rois = (const float*)d_in[1];
    float* out = (float*)d_out;
    const int R = in_sizes[1] / 5;
    prroi_kernel<<<R * 4, 64>>>(feat, rois, out);
}

// round 3
// speedup vs baseline: 5.1981x; 1.8701x over previous
#include <cuda_runtime.h>
#include <cuda_bf16.h>
#include <cstdint>

// PrRoIPool2D(7,7, spatial_scale=0.5)
// features: (N=8, C=256, H=56, W=56) f32
// rois:     (R=256, 5) f32  [b, x1, y1, x2, y2] image coords
// out:      (R, C, 7, 7) f32

#define POOLED 7
#define SCALE 0.5f
#define CC 256
#define HH 56
#define WW 56
#define NCH 128          // channels per block
#define BSTR 36          // padded smem row stride (floats): conflict-free LDS.128

__device__ __forceinline__ float tentG(float t) {
    float u;
    if (t <= 0.0f) { u = t + 1.0f; return 0.5f * u * u; }
    u = 1.0f - t;
    return 1.0f - 0.5f * u * u;
}
__device__ __forceinline__ float tent_int(float s, float e, float i) {
    float a = fminf(fmaxf(s - i, -1.0f), 1.0f);
    float b = fminf(fmaxf(e - i, -1.0f), 1.0f);
    return tentG(b) - tentG(a);
}

struct SmemT {
    float buf[2][NCH][BSTR];   // staged feature windows
    float ixw[POOLED][28];     // compact x weights, window-relative (16B-aligned rows)
    float iy[POOLED][HH];      // y weights with 1/area folded in
};

// ---- templated main body over number of float4 groups in the x-window ----
template<int NJ>
__device__ __forceinline__ void body(
    SmemT* sm, const float4* __restrict__ F4, float* __restrict__ outp,
    int tid, int hlo, int hhi, int base4, float sc)
{
    // ---- stage first row ----
    {
        #pragma unroll
        for (int k = 0; k < NJ; ++k) {
            int i = tid + NCH * k;
            int c = i / NJ, j = i - c * NJ;
            int i4 = base4 + j; i4 = (i4 < 13) ? i4 : 13;
            float4 v = F4[c * (HH * WW / 4) + hlo * (WW / 4) + i4];
            *(float4*)&sm->buf[0][c][j * 4] = v;
        }
    }
    __syncthreads();

    float acc[49];
    #pragma unroll
    for (int k = 0; k < 49; ++k) acc[k] = 0.0f;

    int p = 0;
    for (int h = hlo; h <= hhi; ++h) {
        // prefetch next row into the other buffer
        if (h < hhi) {
            #pragma unroll
            for (int k = 0; k < NJ; ++k) {
                int i = tid + NCH * k;
                int c = i / NJ, j = i - c * NJ;
                int i4 = base4 + j; i4 = (i4 < 13) ? i4 : 13;
                float4 v = F4[c * (HH * WW / 4) + (h + 1) * (WW / 4) + i4];
                *(float4*)&sm->buf[p ^ 1][c][j * 4] = v;
            }
        }
        // load this thread's channel window (conflict-free LDS.128)
        float4 win[NJ];
        #pragma unroll
        for (int j = 0; j < NJ; ++j)
            win[j] = *(const float4*)&sm->buf[p][tid][j * 4];

        // x-integrals for all 7 bins
        float tq[POOLED];
        #pragma unroll
        for (int q = 0; q < POOLED; ++q) {
            float s = 0.0f;
            #pragma unroll
            for (int j = 0; j < NJ; ++j) {
                const float4 wv = *(const float4*)&sm->ixw[q][j * 4];
                s = fmaf(win[j].x, wv.x, s);
                s = fmaf(win[j].y, wv.y, s);
                s = fmaf(win[j].z, wv.z, s);
                s = fmaf(win[j].w, wv.w, s);
            }
            tq[q] = s;
        }
        // y accumulation (uniform skip of zero rows)
        #pragma unroll
        for (int ph = 0; ph < POOLED; ++ph) {
            const float iy = sm->iy[ph][h];
            if (iy != 0.0f) {
                #pragma unroll
                for (int pw = 0; pw < POOLED; ++pw)
                    acc[ph * POOLED + pw] = fmaf(iy, tq[pw], acc[ph * POOLED + pw]);
            }
        }
        __syncthreads();
        p ^= 1;
    }

    // ---- coalesced output via smem ----
    float* sout = (float*)sm;   // reuse staging buffer (>= 128*49 floats)
    #pragma unroll
    for (int k = 0; k < 49; ++k)
        sout[tid * 49 + k] = acc[k] * sc;   // bank-safe: 49*t mod 32 distinct
    __syncthreads();

    const float4* s4 = (const float4*)sout;
    float4* o4 = (float4*)outp;
    #pragma unroll
    for (int k = 0; k < 12; ++k)            // 128*12 = 1536 of 1568 float4
        o4[tid + NCH * k] = s4[tid + NCH * k];
    if (tid < 32)                            // tail 32 float4
        o4[tid + 1536] = s4[tid + 1536];
}

__global__ __launch_bounds__(NCH, 4)
void prroi_kernel(const float* __restrict__ feat,
                  const float* __restrict__ rois,
                  float* __restrict__ out)
{
    __shared__ SmemT sm;
    const int bx  = blockIdx.x;
    const int r   = bx >> 1;
    const int c0  = (bx & 1) * NCH;
    const int tid = threadIdx.x;

    // ---- per-ROI setup (uniform; broadcast loads + redundant ALU) ----
    const float rb  = rois[r * 5 + 0];
    const float rx1 = rois[r * 5 + 1] * SCALE;
    const float ry1 = rois[r * 5 + 2] * SCALE;
    const float rx2 = rois[r * 5 + 3] * SCALE;
    const float ry2 = rois[r * 5 + 4] * SCALE;
    const float bw = (rx2 - rx1) * (1.0f / POOLED);
    const float bh = (ry2 - ry1) * (1.0f / POOLED);
    const float area = bw * bh;
    const float sc = (area > 0.0f) ? (1.0f / fmaxf(area, 1e-12f)) : 0.0f;

    int hlo = (int)ceilf(ry1 - 1.0f);  if (hlo < 0) hlo = 0;
    int hhi = (int)floorf(ry2 + 1.0f); if (hhi > HH - 1) hhi = HH - 1;
    int wlo = (int)ceilf(rx1 - 1.0f);  if (wlo < 0) wlo = 0;
    const int wbase = wlo & ~3;
    const int base4 = wbase >> 2;
    int whi = (int)floorf(rx2 + 1.0f); if (whi > WW - 1) whi = WW - 1;
    int nj = ((whi - wbase + 1) + 3) >> 2;   // float4 groups needed
    if (nj < 1) nj = 1; if (nj > 7) nj = 7;

    // ---- weight tables ----
    for (int t = tid; t < POOLED * 28; t += NCH) {
        int q = t / 28, tt = t - q * 28;
        int w = wbase + tt;
        float xs = rx1 + q * bw;
        sm.ixw[q][tt] = (w < WW) ? tent_int(xs, xs + bw, (float)w) : 0.0f;
    }
    for (int t = tid; t < POOLED * HH; t += NCH) {
        int q = t / HH, hh = t - q * HH;
        float ys = ry1 + q * bh;
        sm.iy[q][hh] = tent_int(ys, ys + bh, (float)hh);
    }
    // NOTE: no barrier here; body<> begins with a barrier after first-row staging,
    // which also covers the weight-table fill.

    const float4* F4 =
        (const float4*)(feat + ((size_t)(int)rb * CC + c0) * (HH * WW));
    float* outp = out + ((size_t)r * CC + c0) * 49;

    switch (nj) {
        case 7:  body<7>(&sm, F4, outp, tid, hlo, hhi, base4, sc); break;
        case 6:  body<6>(&sm, F4, outp, tid, hlo, hhi, base4, sc); break;
        case 5:  body<5>(&sm, F4, outp, tid, hlo, hhi, base4, sc); break;
        default: body<4>(&sm, F4, outp, tid, hlo, hhi, base4, sc); break;
    }
}

extern "C" void kernel_launch(void* const* d_in, const int* in_sizes, int n_in,
                              void* d_out, int out_size) {
    const float* feat = (const float*)d_in[0];
    const float* rois = (const float*)d_in[1];
    float* out = (float*)d_out;
    const int R = in_sizes[1] / 5;
    prroi_kernel<<<R * 2, NCH>>>(feat, rois, out);
}